// round 2
// baseline (speedup 1.0000x reference)
#include <cuda_runtime.h>
#include <cstdint>

#define D 128
#define LAYERS 3
#define MAXN 100000
#define MAXG 2048
#define BR 64          // GEMM rows per block
#define BN_EPS 1e-5f

// ---------------- scratch (device globals; no runtime allocation) ------------
__device__ float    g_h[LAYERS][MAXN * D];   // post-BN layer outputs (and pre-BN temp)
__device__ float    g_agg[MAXN * D];         // h + sum_neighbors
__device__ float    g_m1[MAXN * D];          // hidden MLP activation
__device__ float    g_colsum[D];
__device__ float    g_colsq[D];
__device__ unsigned g_outmax[MAXG * LAYERS * D];

// ---------------- kernels ----------------------------------------------------

// agg = h_prev (copy), plus zero the BN stat accumulators
__global__ void copy_init_kernel(const float* __restrict__ x, int layer, int n4)
{
    int i = blockIdx.x * blockDim.x + threadIdx.x;
    const float* src = (layer == 0) ? x : g_h[layer - 1];
    if (i < n4) ((float4*)g_agg)[i] = ((const float4*)src)[i];
    if (i < D) { g_colsum[i] = 0.f; g_colsq[i] = 0.f; }
}

// one warp per edge: lane handles a float4 chunk of the 128-float row
__global__ void edge_scatter_kernel(const int* __restrict__ ei,
                                    const float* __restrict__ x,
                                    int layer, int nedges)
{
    int t = blockIdx.x * blockDim.x + threadIdx.x;
    int e = t >> 5;
    if (e >= nedges) return;
    int lane = t & 31;
    const float* h = (layer == 0) ? x : g_h[layer - 1];
    int src = ei[e];
    int dst = ei[nedges + e];
    float4 v = *(const float4*)(h + (size_t)src * D + lane * 4);
    float* p = g_agg + (size_t)dst * D + lane * 4;
    // return value unused -> ptxas emits RED.E.ADD.F32
    atomicAdd(p + 0, v.x);
    atomicAdd(p + 1, v.y);
    atomicAdd(p + 2, v.z);
    atomicAdd(p + 3, v.w);
}

// C = relu(A @ W + b), optional column sum/sumsq accumulation (BN stats)
__global__ __launch_bounds__(256) void gemm_relu_kernel(
    const float* __restrict__ A, const float* __restrict__ W,
    const float* __restrict__ bias, float* __restrict__ C,
    int n, int doStats)
{
    extern __shared__ float sm[];
    float* As = sm;              // [BR][128]
    float* Ws = sm + BR * D;     // [128][128]
    int t = threadIdx.x;
    int row0 = blockIdx.x * BR;

    // load W (128x128) to smem, coalesced float4
    for (int i = t; i < D * D / 4; i += 256)
        ((float4*)Ws)[i] = ((const float4*)W)[i];
    // load A tile (BRx128), coalesced float4, zero-pad OOB rows
    for (int i = t; i < BR * D / 4; i += 256) {
        int r = i >> 5, c4 = i & 31;
        int gr = row0 + r;
        float4 v = make_float4(0.f, 0.f, 0.f, 0.f);
        if (gr < n) v = ((const float4*)(A + (size_t)gr * D))[c4];
        ((float4*)(As + r * D))[c4] = v;
    }
    __syncthreads();

    int cg = (t & 31) * 4;   // column base (lane -> cols, coalesced stores)
    int rg = (t >> 5) * 8;   // row base (warp -> rows, smem broadcasts)
    float acc[8][4];
#pragma unroll
    for (int r = 0; r < 8; r++)
#pragma unroll
        for (int c = 0; c < 4; c++) acc[r][c] = 0.f;

#pragma unroll 8
    for (int k = 0; k < D; k++) {
        float4 w = *(float4*)(Ws + k * D + cg);
#pragma unroll
        for (int r = 0; r < 8; r++) {
            float a = As[(rg + r) * D + k];
            acc[r][0] += a * w.x;
            acc[r][1] += a * w.y;
            acc[r][2] += a * w.z;
            acc[r][3] += a * w.w;
        }
    }

    float4 b = *(const float4*)(bias + cg);
    float s0 = 0.f, s1 = 0.f, s2 = 0.f, s3 = 0.f;
    float q0 = 0.f, q1 = 0.f, q2 = 0.f, q3 = 0.f;
#pragma unroll
    for (int r = 0; r < 8; r++) {
        int gr = row0 + rg + r;
        if (gr < n) {
            float4 o;
            o.x = fmaxf(acc[r][0] + b.x, 0.f);
            o.y = fmaxf(acc[r][1] + b.y, 0.f);
            o.z = fmaxf(acc[r][2] + b.z, 0.f);
            o.w = fmaxf(acc[r][3] + b.w, 0.f);
            *(float4*)(C + (size_t)gr * D + cg) = o;
            if (doStats) {
                s0 += o.x; s1 += o.y; s2 += o.z; s3 += o.w;
                q0 += o.x * o.x; q1 += o.y * o.y; q2 += o.z * o.z; q3 += o.w * o.w;
            }
        }
    }
    if (doStats) {
        atomicAdd(&g_colsum[cg + 0], s0); atomicAdd(&g_colsum[cg + 1], s1);
        atomicAdd(&g_colsum[cg + 2], s2); atomicAdd(&g_colsum[cg + 3], s3);
        atomicAdd(&g_colsq[cg + 0], q0);  atomicAdd(&g_colsq[cg + 1], q1);
        atomicAdd(&g_colsq[cg + 2], q2);  atomicAdd(&g_colsq[cg + 3], q3);
    }
}

// in-place batchnorm on g_h[layer]
__global__ void bn_apply_kernel(int layer, const float* __restrict__ gamma,
                                const float* __restrict__ beta, int n, float invN)
{
    int i = blockIdx.x * blockDim.x + threadIdx.x;  // over n*32 float4s
    if (i >= n * (D / 4)) return;
    int c = (i & 31) * 4;
    float4 v = ((float4*)g_h[layer])[i];
    float4 mu, var, sc, bt;
    mu.x = g_colsum[c + 0] * invN; mu.y = g_colsum[c + 1] * invN;
    mu.z = g_colsum[c + 2] * invN; mu.w = g_colsum[c + 3] * invN;
    var.x = g_colsq[c + 0] * invN - mu.x * mu.x;
    var.y = g_colsq[c + 1] * invN - mu.y * mu.y;
    var.z = g_colsq[c + 2] * invN - mu.z * mu.z;
    var.w = g_colsq[c + 3] * invN - mu.w * mu.w;
    sc.x = gamma[c + 0] * rsqrtf(var.x + BN_EPS);
    sc.y = gamma[c + 1] * rsqrtf(var.y + BN_EPS);
    sc.z = gamma[c + 2] * rsqrtf(var.z + BN_EPS);
    sc.w = gamma[c + 3] * rsqrtf(var.w + BN_EPS);
    bt.x = beta[c + 0]; bt.y = beta[c + 1]; bt.z = beta[c + 2]; bt.w = beta[c + 3];
    v.x = (v.x - mu.x) * sc.x + bt.x;
    v.y = (v.y - mu.y) * sc.y + bt.y;
    v.z = (v.z - mu.z) * sc.z + bt.z;
    v.w = (v.w - mu.w) * sc.w + bt.w;
    ((float4*)g_h[layer])[i] = v;
}

__global__ void init_max_kernel(int total)
{
    int i = blockIdx.x * blockDim.x + threadIdx.x;
    if (i < total) g_outmax[i] = 0u;  // 0 encodes below every finite float
}

__device__ __forceinline__ unsigned f2ord(float v)
{
    unsigned u = __float_as_uint(v);
    return (u & 0x80000000u) ? ~u : (u | 0x80000000u);
}

__global__ void seg_max_kernel(const int* __restrict__ batch, int n)
{
    int t = blockIdx.x * blockDim.x + threadIdx.x;
    int node = t / (LAYERS * D);
    if (node >= n) return;
    int j = t - node * (LAYERS * D);
    int l = j >> 7, d = j & 127;
    float v = g_h[l][(size_t)node * D + d];
    int g = batch[node];
    atomicMax(&g_outmax[g * (LAYERS * D) + j], f2ord(v));  // -> RED.MAX.U32
}

__global__ void decode_kernel(float* __restrict__ out, int total)
{
    int i = blockIdx.x * blockDim.x + threadIdx.x;
    if (i >= total) return;
    unsigned u = g_outmax[i];
    unsigned bits = (u & 0x80000000u) ? (u ^ 0x80000000u) : ~u;
    out[i] = __uint_as_float(bits);
}

// ---------------- launch -----------------------------------------------------

extern "C" void kernel_launch(void* const* d_in, const int* in_sizes, int n_in,
                              void* d_out, int out_size)
{
    const float* x     = (const float*)d_in[0];
    const int*   ei    = (const int*)d_in[1];    // int32: JAX x64 disabled
    const int*   batch = (const int*)d_in[2];    // int32
    const float* W1    = (const float*)d_in[3];
    const float* b1    = (const float*)d_in[4];
    const float* W2    = (const float*)d_in[5];
    const float* b2    = (const float*)d_in[6];
    const float* gamma = (const float*)d_in[7];
    const float* beta  = (const float*)d_in[8];
    float* out = (float*)d_out;

    int n  = in_sizes[0] / D;       // 100000
    int ne = in_sizes[1] / 2;       // 1600000
    float invN = 1.0f / (float)n;

    float *p_agg, *p_m1, *p_h;
    cudaGetSymbolAddress((void**)&p_agg, g_agg);
    cudaGetSymbolAddress((void**)&p_m1,  g_m1);
    cudaGetSymbolAddress((void**)&p_h,   g_h);

    int smem = (BR * D + D * D) * (int)sizeof(float);  // 96KB
    cudaFuncSetAttribute(gemm_relu_kernel,
                         cudaFuncAttributeMaxDynamicSharedMemorySize, smem);

    int n4 = n * (D / 4);
    int copyBlocks = (n4 + 255) / 256;
    int edgeBlocks = (ne * 32 + 255) / 256;
    int gemmBlocks = (n + BR - 1) / BR;

    for (int i = 0; i < LAYERS; i++) {
        copy_init_kernel<<<copyBlocks, 256>>>(x, i, n4);
        edge_scatter_kernel<<<edgeBlocks, 256>>>(ei, x, i, ne);
        gemm_relu_kernel<<<gemmBlocks, 256, smem>>>(
            p_agg, W1 + i * D * D, b1 + i * D, p_m1, n, 0);
        gemm_relu_kernel<<<gemmBlocks, 256, smem>>>(
            p_m1, W2 + i * D * D, b2 + i * D, p_h + (size_t)i * MAXN * D, n, 1);
        bn_apply_kernel<<<copyBlocks, 256>>>(i, gamma + i * D, beta + i * D, n, invN);
    }

    int totOut = out_size;  // G * 384
    init_max_kernel<<<(totOut + 255) / 256, 256>>>(totOut);
    int segThreads = n * LAYERS * D;
    seg_max_kernel<<<(segThreads + 255) / 256, 256>>>(batch, n);
    decode_kernel<<<(totOut + 255) / 256, 256>>>(out, totOut);
}